// round 5
// baseline (speedup 1.0000x reference)
#include <cuda_runtime.h>
#include <cstdint>

// SpatialCorrelationSampler: out[b, dy*9+dx, h, w] =
//   sum_c in1[b,c,h,w] * in2_zeropad4[b,c,h+dy,w+dx],  dy,dx in [0,9)
// Shapes: in1,in2 (B=4, C=256, H=128, W=128) fp32; out (B, 81, H, W) fp32.
//
// Round 5: f32x2 done right. All register pairs come FREE from 16B smem
// loads (ulonglong2). Even dx pairs r normally; odd dx pairs the *a* side
// (pixels (1,2)(3,4)(5,6)) so the r-pair start index is even again.
// Only 3 pack MOV-pairs per channel; px0/px7 of odd dx are scalar FFMA.
// fma-pipe inst/channel: 40 (was 72 scalar).

namespace {

constexpr int C = 256, H = 128, W = 128;
constexpr int PATCH = 9, PAD = 4;

constexpr int TH = 8;            // tile rows
constexpr int TW = 32;           // tile cols
constexpr int CC = 8;            // channels per smem chunk
constexpr int S2H = TH + 8;      // 16
constexpr int S2W = TW + 8;      // 40
constexpr int S1P = 36;          // padded s1 row stride (floats)
constexpr int S2P = 44;          // padded s2 row stride (floats)
constexpr int NTHREADS = 4 * TH * PATCH;   // 288
constexpr int NCHUNK = C / CC;             // 32
constexpr int CHUNK_GBYTES = CC * H * W * 4;

constexpr int S1_REAL_V4 = CC * TH * (TW / 4);     // 512
constexpr int S2_REAL_V4 = CC * S2H * (S2W / 4);   // 1280
constexpr int TOT_V4 = S1_REAL_V4 + S2_REAL_V4;    // 1792
constexpr int SLOTS = (TOT_V4 + NTHREADS - 1) / NTHREADS;  // 7

constexpr int S1_FLOATS = CC * TH * S1P;            // 2304
constexpr int S2_FLOATS = CC * S2H * S2P;           // 5632
constexpr int STAGE_FLOATS = S1_FLOATS + S2_FLOATS; // 7936
constexpr int STAGES = 3;
constexpr int SMEM_BYTES = STAGES * STAGE_FLOATS * 4;   // 95232

__device__ __forceinline__ uint64_t fma2(uint64_t a, uint64_t b, uint64_t c) {
    uint64_t d;
    asm("fma.rn.f32x2 %0, %1, %2, %3;" : "=l"(d) : "l"(a), "l"(b), "l"(c));
    return d;
}
__device__ __forceinline__ float lo32(uint64_t v) {
    return __uint_as_float((uint32_t)v);
}
__device__ __forceinline__ float hi32(uint64_t v) {
    return __uint_as_float((uint32_t)(v >> 32));
}
// build pair (hi of x, lo of y) -> {a[2m+1], a[2m+2]}
__device__ __forceinline__ uint64_t midpair(uint64_t x, uint64_t y) {
    return (x >> 32) | (y << 32);
}

__device__ __forceinline__ void cp16(uint32_t dst_smem, const void* src) {
    asm volatile("cp.async.cg.shared.global [%0], [%1], 16;"
                 :: "r"(dst_smem), "l"(src));
}
__device__ __forceinline__ void cp_commit() {
    asm volatile("cp.async.commit_group;" ::: "memory");
}
__device__ __forceinline__ void cp_wait1() {
    asm volatile("cp.async.wait_group 1;" ::: "memory");
}

__global__ __launch_bounds__(NTHREADS, 2)
void corr_kernel(const float* __restrict__ in1,
                 const float* __restrict__ in2,
                 float* __restrict__ out) {
    extern __shared__ float smem[];
    const uint32_t smem_u32 = (uint32_t)__cvta_generic_to_shared(smem);

    const int b  = blockIdx.z;
    const int h0 = blockIdx.y * TH;
    const int w0 = blockIdx.x * TW;
    const int tid = threadIdx.x;

    // ---------------- copy-slot precompute --------------------------------
    uint32_t soff[SLOTS];
    uint32_t goff[SLOTS];   // ~0 = skip
    bool     is1[SLOTS];
#pragma unroll
    for (int i = 0; i < SLOTS; ++i) {
        int f = tid + i * NTHREADS;
        goff[i] = 0xFFFFFFFFu;
        soff[i] = 0;
        is1[i]  = false;
        if (f < S1_REAL_V4) {
            int c = f >> 6, rem = f & 63;
            int row = rem >> 3, col4 = rem & 7;
            soff[i] = ((c * TH + row) * S1P + col4 * 4) * 4;
            goff[i] = (uint32_t)((((b * C + c) * H + (h0 + row)) * W
                                  + w0 + col4 * 4) * 4);
            is1[i] = true;
        } else if (f < TOT_V4) {
            int u = f - S1_REAL_V4;
            int c = u / 160, rem = u % 160;
            int row = rem / 10, col4 = rem % 10;
            soff[i] = (S1_FLOATS + (c * S2H + row) * S2P + col4 * 4) * 4;
            int gy = h0 + row - PAD;
            int gx = w0 + col4 * 4 - PAD;      // 16B aligned: all-in or all-out
            if (gy >= 0 && gy < H && gx >= 0 && gx < W) {
                goff[i] = (uint32_t)((((b * C + c) * H + gy) * W + gx) * 4);
            } else {
                float4 z = make_float4(0.f, 0.f, 0.f, 0.f);
#pragma unroll
                for (int s = 0; s < STAGES; ++s)
                    *(float4*)((char*)smem + s * STAGE_FLOATS * 4 + soff[i]) = z;
            }
        }
    }

    auto issue_chunk = [&](int ch) {
        uint32_t sbase = smem_u32 + (uint32_t)((ch % STAGES) * STAGE_FLOATS * 4);
        size_t gchunk = (size_t)ch * CHUNK_GBYTES;
#pragma unroll
        for (int i = 0; i < SLOTS; ++i) {
            if (goff[i] != 0xFFFFFFFFu) {
                const char* base = is1[i] ? (const char*)in1 : (const char*)in2;
                cp16(sbase + soff[i], base + gchunk + goff[i]);
            }
        }
        cp_commit();
    };

    issue_chunk(0);
    issue_chunk(1);

    // ---------------- compute-role mapping --------------------------------
    const int sx = tid & 3;          // 8-pixel strip (col = sx*8)
    const int hy = (tid >> 2) & 7;   // row within tile
    const int dy = tid >> 5;         // 0..8

    const int a_off = hy * S1P + sx * 8;          // 16B aligned (144,32)
    const int r_off = (hy + dy) * S2P + sx * 8;   // 16B aligned (176,32)

    // accumulators (all packed values are bit-aliased float pairs)
    uint64_t accE[5][4];     // even dx {0,2,4,6,8}, pixel pairs (0,1)(2,3)(4,5)(6,7)
    uint64_t accO[4][3];     // odd dx {1,3,5,7}, pixel pairs (1,2)(3,4)(5,6)
    float    accS[4][2];     // odd dx, scalar px0 / px7
#pragma unroll
    for (int i = 0; i < 5; ++i)
#pragma unroll
        for (int q = 0; q < 4; ++q) accE[i][q] = 0ull;
#pragma unroll
    for (int i = 0; i < 4; ++i) {
#pragma unroll
        for (int m = 0; m < 3; ++m) accO[i][m] = 0ull;
        accS[i][0] = accS[i][1] = 0.f;
    }

    for (int ch = 0; ch < NCHUNK; ++ch) {
        cp_wait1();                 // group ch landed (ch, ch+1 pending)
        __syncthreads();            // stage ch visible; stage (ch+2)%3 free

        if (ch + 2 < NCHUNK) issue_chunk(ch + 2);
        else cp_commit();

        const float* st  = smem + (ch % STAGES) * STAGE_FLOATS;
        const float* s1f = st;
        const float* s2f = st + S1_FLOATS;

#pragma unroll
        for (int c = 0; c < CC; ++c) {
            const float* p1 = s1f + c * (TH * S1P) + a_off;
            const float* p2 = s2f + c * (S2H * S2P) + r_off;

            // a: 8 floats = 4 aligned pairs (free from LDS.128)
            ulonglong2 Aa = *(const ulonglong2*)(p1);
            ulonglong2 Ab = *(const ulonglong2*)(p1 + 4);
            uint64_t ae0 = Aa.x, ae1 = Aa.y, ae2 = Ab.x, ae3 = Ab.y;
            // a odd pairs (a1,a2)(a3,a4)(a5,a6): 3 packs per channel
            uint64_t ao0 = midpair(ae0, ae1);
            uint64_t ao1 = midpair(ae1, ae2);
            uint64_t ao2 = midpair(ae2, ae3);
            float a0 = lo32(ae0), a7 = hi32(ae3);

            // r: 16 floats = 8 aligned pairs (free)
            ulonglong2 Ra = *(const ulonglong2*)(p2);
            ulonglong2 Rb = *(const ulonglong2*)(p2 + 4);
            ulonglong2 Rc = *(const ulonglong2*)(p2 + 8);
            ulonglong2 Rd = *(const ulonglong2*)(p2 + 12);
            uint64_t re[8] = {Ra.x, Ra.y, Rb.x, Rb.y, Rc.x, Rc.y, Rd.x, Rd.y};

            // even dx: accE[e][q] += ae[q] * re[q + e]
#pragma unroll
            for (int e = 0; e < 5; ++e) {
                accE[e][0] = fma2(ae0, re[e + 0], accE[e][0]);
                accE[e][1] = fma2(ae1, re[e + 1], accE[e][1]);
                accE[e][2] = fma2(ae2, re[e + 2], accE[e][2]);
                accE[e][3] = fma2(ae3, re[e + 3], accE[e][3]);
            }
            // odd dx = 2d+1: accO[d][m] += ao[m] * re[m + d + 1]
#pragma unroll
            for (int d = 0; d < 4; ++d) {
                accO[d][0] = fma2(ao0, re[d + 1], accO[d][0]);
                accO[d][1] = fma2(ao1, re[d + 2], accO[d][1]);
                accO[d][2] = fma2(ao2, re[d + 3], accO[d][2]);
                // scalar edges: px0 uses r[dx]=hi(re[d]); px7 uses r[7+dx]=lo(re[d+4])
                accS[d][0] = fmaf(a0, hi32(re[d]),     accS[d][0]);
                accS[d][1] = fmaf(a7, lo32(re[d + 4]), accS[d][1]);
            }
        }
    }

    // ---------------- epilogue --------------------------------------------
    const int h = h0 + hy;
    const int wb = w0 + sx * 8;
#pragma unroll
    for (int dx = 0; dx < 9; ++dx) {
        float v[8];
        if ((dx & 1) == 0) {
            int e = dx >> 1;
#pragma unroll
            for (int q = 0; q < 4; ++q) {
                v[2 * q]     = lo32(accE[e][q]);
                v[2 * q + 1] = hi32(accE[e][q]);
            }
        } else {
            int d = dx >> 1;
            v[0] = accS[d][0];
#pragma unroll
            for (int m = 0; m < 3; ++m) {
                v[2 * m + 1] = lo32(accO[d][m]);
                v[2 * m + 2] = hi32(accO[d][m]);
            }
            v[7] = accS[d][1];
        }
        int p = dy * 9 + dx;
        float* op = out + (((size_t)b * (PATCH * PATCH) + p) * H + h) * W + wb;
        *(float4*)(op)     = make_float4(v[0], v[1], v[2], v[3]);
        *(float4*)(op + 4) = make_float4(v[4], v[5], v[6], v[7]);
    }
}

}  // namespace

extern "C" void kernel_launch(void* const* d_in, const int* in_sizes, int n_in,
                              void* d_out, int out_size) {
    const float* in1 = (const float*)d_in[0];
    const float* in2 = (const float*)d_in[1];
    float* out = (float*)d_out;

    cudaFuncSetAttribute(corr_kernel,
                         cudaFuncAttributeMaxDynamicSharedMemorySize,
                         SMEM_BYTES);

    int B = in_sizes[0] / (C * H * W);   // = 4
    dim3 grid(W / TW, H / TH, B);        // (4, 16, 4) = 256 blocks
    corr_kernel<<<grid, NTHREADS, SMEM_BYTES>>>(in1, in2, out);
}